// round 1
// baseline (speedup 1.0000x reference)
#include <cuda_runtime.h>

// EarlyRewardLoss: N=4096, T=365, C=32
// loss = ALPHA * mean_n sum_t (-yh)*Pt  -  (1-ALPHA) * mean_n sum_t Pt*exp(yh)*(1 - t/T)
// Pt[t] = deltas[t+1] * B[t]  (t < T-1),  Pt[T-1] = B[T-1],  plus EPS/T
// B[t]  = prod_{j=1..t} (1 - deltas[j])   (exclusive prefix product)

#define NROWS 4096
#define TLEN  365
#define CCLS  32
#define CHUNK 12   // 32 lanes * 12 = 384 >= 365

static constexpr float ALPHA_F  = 0.5f;
static constexpr float EPS_O_T  = 10.0f / 365.0f;
static constexpr float INV_T    = 1.0f / 365.0f;

__device__ float g_partial[NROWS];

__global__ __launch_bounds__(256) void row_kernel(
    const float* __restrict__ lcp,   // [N, T, C]
    const float* __restrict__ ps,    // [N, T]
    const int*   __restrict__ yt)    // [N, T]
{
    const int warp_id = (blockIdx.x * blockDim.x + threadIdx.x) >> 5;
    const int lane    = threadIdx.x & 31;
    if (warp_id >= NROWS) return;
    const int n = warp_id;
    const int s = lane * CHUNK;

    const float* psrow  = ps  + (long)n * TLEN;
    const int*   ytrow  = yt  + (long)n * TLEN;
    const float* lcprow = lcp + (long)n * TLEN * CCLS;

    // ---- load deltas[t+1], build factors q[t] = (t < T-1) ? 1-deltas[t+1] : 1
    float dnext[CHUNK];
    float q[CHUNK];
#pragma unroll
    for (int k = 0; k < CHUNK; k++) {
        int t = s + k;
        float dn = (t + 1 < TLEN) ? __ldg(psrow + t + 1) : 0.0f;
        dnext[k] = dn;
        q[k] = (t < TLEN - 1) ? (1.0f - dn) : 1.0f;
    }

    // ---- issue the gathers EARLY so DRAM latency overlaps the scan math
    int   yv[CHUNK];
    float yh[CHUNK];
#pragma unroll
    for (int k = 0; k < CHUNK; k++) {
        int t = s + k;
        yv[k] = (t < TLEN) ? __ldg(ytrow + t) : 0;
    }
#pragma unroll
    for (int k = 0; k < CHUNK; k++) {
        int t = s + k;
        yh[k] = (t < TLEN) ? __ldg(lcprow + t * CCLS + yv[k]) : 0.0f;
    }

    // ---- local exclusive prefix products
    float pref[CHUNK];
    float prod = 1.0f;
#pragma unroll
    for (int k = 0; k < CHUNK; k++) { pref[k] = prod; prod *= q[k]; }

    // ---- warp inclusive product scan of lane totals, then shift to exclusive
    float v = prod;
#pragma unroll
    for (int off = 1; off < 32; off <<= 1) {
        float up = __shfl_up_sync(0xffffffffu, v, off);
        if (lane >= off) v *= up;
    }
    float base = __shfl_up_sync(0xffffffffu, v, 1);
    if (lane == 0) base = 1.0f;

    // ---- fused epilogue: Pt, exp, weighted sums
    float ce = 0.0f, er = 0.0f;
#pragma unroll
    for (int k = 0; k < CHUNK; k++) {
        int t = s + k;
        if (t < TLEN) {
            float B  = base * pref[k];
            float Pt = ((t < TLEN - 1) ? dnext[k] * B : B) + EPS_O_T;
            float p  = __expf(yh[k]);
            er = fmaf(Pt * p, 1.0f - (float)t * INV_T, er);
            ce = fmaf(-yh[k], Pt, ce);
        }
    }

    // ---- warp reduce
#pragma unroll
    for (int off = 16; off; off >>= 1) {
        ce += __shfl_down_sync(0xffffffffu, ce, off);
        er += __shfl_down_sync(0xffffffffu, er, off);
    }
    if (lane == 0)
        g_partial[n] = ALPHA_F * ce - (1.0f - ALPHA_F) * er;
}

__global__ __launch_bounds__(256) void reduce_kernel(float* __restrict__ out)
{
    __shared__ float sh[256];
    const int tid = threadIdx.x;
    float s = 0.0f;
#pragma unroll
    for (int i = 0; i < NROWS / 256; i++)
        s += g_partial[tid + i * 256];
    sh[tid] = s;
    __syncthreads();
    for (int w = 128; w >= 32; w >>= 1) {
        if (tid < w) sh[tid] += sh[tid + w];
        __syncthreads();
    }
    if (tid < 32) {
        float v = sh[tid];
#pragma unroll
        for (int off = 16; off; off >>= 1)
            v += __shfl_down_sync(0xffffffffu, v, off);
        if (tid == 0) out[0] = v * (1.0f / (float)NROWS);
    }
}

extern "C" void kernel_launch(void* const* d_in, const int* in_sizes, int n_in,
                              void* d_out, int out_size)
{
    const float* lcp = (const float*)d_in[0];  // [N,T,C] f32
    const float* ps  = (const float*)d_in[1];  // [N,T]   f32
    const int*   yt  = (const int*)  d_in[2];  // [N,T]   i32
    float* out = (float*)d_out;

    // 8 warps per block -> 512 blocks cover 4096 rows
    row_kernel<<<NROWS / 8, 256>>>(lcp, ps, yt);
    reduce_kernel<<<1, 256>>>(out);
}

// round 3
// speedup vs baseline: 1.0536x; 1.0536x over previous
#include <cuda_runtime.h>

// EarlyRewardLoss: N=4096, T=365, C=32
// loss = ALPHA * mean_n sum_t (-yh)*Pt  -  (1-ALPHA) * mean_n sum_t Pt*exp(yh)*(1 - t/T)
// Pt[t] = deltas[t+1] * B[t]  (t < T-1),  Pt[T-1] = B[T-1],  plus EPS/T
// B[t]  = prod_{j=1..t} (1 - deltas[j])   (exclusive warp product scan)

#define NROWS 4096
#define TLEN  365
#define CCLS  32
#define CHUNK 12            // 32 lanes * 12 = 384 >= 365
#define NBLK  (NROWS / 8)   // 8 warps (rows) per 256-thread block -> 512 blocks

static constexpr float ALPHA_F = 0.5f;
static constexpr float EPS_O_T = 10.0f / 365.0f;
static constexpr float INV_T   = 1.0f / 365.0f;

__device__ float        g_block[NBLK];
__device__ unsigned int g_count = 0;   // last block resets it -> replay-safe

__global__ __launch_bounds__(256) void fused_kernel(
    const float* __restrict__ lcp,   // [N, T, C]
    const float* __restrict__ ps,    // [N, T]
    const int*   __restrict__ yt,    // [N, T]
    float* __restrict__ out)
{
    const int wid  = threadIdx.x >> 5;
    const int lane = threadIdx.x & 31;
    const int n    = blockIdx.x * 8 + wid;
    const int s    = lane * CHUNK;

    const float* psrow  = ps  + (long)n * TLEN;
    const int*   ytrow  = yt  + (long)n * TLEN;
    const float* lcprow = lcp + (long)n * TLEN * CCLS;

    // ---------- batched, unconditional clamped scalar loads ----------
    // (T=365 is odd -> row base is only 4B-aligned; vector loads are illegal)
    float pv[CHUNK];
    int   yv[CHUNK];
#pragma unroll
    for (int k = 0; k < CHUNK; k++) {
        int tc = min(s + k, TLEN - 1);
        pv[k] = __ldg(psrow + tc);
    }
#pragma unroll
    for (int k = 0; k < CHUNK; k++) {
        int tc = min(s + k, TLEN - 1);
        yv[k] = __ldg(ytrow + tc);
    }

    // ---------- gathers: unconditional, clamped, back-to-back ----------
    float yh[CHUNK];
#pragma unroll
    for (int k = 0; k < CHUNK; k++) {
        int tc = min(s + k, TLEN - 1);
        yh[k] = __ldg(lcprow + tc * CCLS + yv[k]);
    }

    // ps[s+12] lives in lane+1's pv[0]
    float pnext = __shfl_down_sync(0xffffffffu, pv[0], 1);

    // ---------- factors q[t] = (t < T-1) ? 1 - ps[t+1] : 1 ----------
    float q[CHUNK];
#pragma unroll
    for (int k = 0; k < CHUNK; k++) {
        int t = s + k;
        float pn = (k < CHUNK - 1) ? pv[k + 1] : pnext;
        q[k] = (t < TLEN - 1) ? (1.0f - pn) : 1.0f;
    }

    // ---------- local exclusive prefix products ----------
    float pref[CHUNK];
    float prod = 1.0f;
#pragma unroll
    for (int k = 0; k < CHUNK; k++) { pref[k] = prod; prod *= q[k]; }

    // ---------- warp product scan (inclusive -> exclusive) ----------
    float v = prod;
#pragma unroll
    for (int off = 1; off < 32; off <<= 1) {
        float up = __shfl_up_sync(0xffffffffu, v, off);
        if (lane >= off) v *= up;
    }
    float base = __shfl_up_sync(0xffffffffu, v, 1);
    if (lane == 0) base = 1.0f;

    // ---------- fused epilogue ----------
    float ce = 0.0f, er = 0.0f;
#pragma unroll
    for (int k = 0; k < CHUNK; k++) {
        int t = s + k;
        if (t < TLEN) {
            float B  = base * pref[k];
            float d  = 1.0f - q[k];                       // = ps[t+1] when t < T-1
            float Pt = ((t < TLEN - 1) ? d * B : B) + EPS_O_T;
            float p  = __expf(yh[k]);
            er = fmaf(Pt * p, 1.0f - (float)t * INV_T, er);
            ce = fmaf(-yh[k], Pt, ce);
        }
    }

    // ---------- warp reduce -> per-row value ----------
#pragma unroll
    for (int off = 16; off; off >>= 1) {
        ce += __shfl_down_sync(0xffffffffu, ce, off);
        er += __shfl_down_sync(0xffffffffu, er, off);
    }

    __shared__ float ssum[8];
    __shared__ bool  s_last;
    if (lane == 0)
        ssum[wid] = ALPHA_F * ce - (1.0f - ALPHA_F) * er;
    __syncthreads();

    // ---------- block sum + last-block final reduction ----------
    if (threadIdx.x == 0) {
        float bs = 0.0f;
#pragma unroll
        for (int i = 0; i < 8; i++) bs += ssum[i];
        g_block[blockIdx.x] = bs;
        __threadfence();
        unsigned int ticket = atomicAdd(&g_count, 1u);
        s_last = (ticket == NBLK - 1);
    }
    __syncthreads();

    if (s_last) {
        float t0 = g_block[threadIdx.x] + g_block[threadIdx.x + 256];
        __shared__ float sh[256];
        sh[threadIdx.x] = t0;
        __syncthreads();
        for (int w = 128; w >= 32; w >>= 1) {
            if (threadIdx.x < w) sh[threadIdx.x] += sh[threadIdx.x + w];
            __syncthreads();
        }
        if (threadIdx.x < 32) {
            float r = sh[threadIdx.x];
#pragma unroll
            for (int off = 16; off; off >>= 1)
                r += __shfl_down_sync(0xffffffffu, r, off);
            if (threadIdx.x == 0) {
                out[0] = r * (1.0f / (float)NROWS);
                g_count = 0;               // reset for next graph replay
            }
        }
    }
}

extern "C" void kernel_launch(void* const* d_in, const int* in_sizes, int n_in,
                              void* d_out, int out_size)
{
    const float* lcp = (const float*)d_in[0];  // [N,T,C] f32
    const float* ps  = (const float*)d_in[1];  // [N,T]   f32
    const int*   yt  = (const int*)  d_in[2];  // [N,T]   i32
    float* out = (float*)d_out;

    fused_kernel<<<NBLK, 256>>>(lcp, ps, yt, out);
}

// round 4
// speedup vs baseline: 1.0737x; 1.0191x over previous
#include <cuda_runtime.h>

// EarlyRewardLoss: N=4096, T=365, C=32
// Strip-interleaved layout: lane owns t = 32*k + lane, k = 0..11.
// Per unroll step a warp's gathers cover 32 consecutive 128B lcp rows
// (4KB contiguous) for DRAM page locality + coalesced ps/yt loads.

#define NROWS 4096
#define TLEN  365
#define CCLS  32
#define STRIPS 12           // 12*32 = 384 >= 365
#define NBLK  (NROWS / 8)   // 8 warps (rows) per 256-thread block

static constexpr float ALPHA_F = 0.5f;
static constexpr float EPS_O_T = 10.0f / 365.0f;
static constexpr float INV_T   = 1.0f / 365.0f;

__device__ float        g_block[NBLK];
__device__ unsigned int g_count = 0;   // last block resets it -> replay-safe

__global__ __launch_bounds__(256) void fused_kernel(
    const float* __restrict__ lcp,   // [N, T, C]
    const float* __restrict__ ps,    // [N, T]
    const int*   __restrict__ yt,    // [N, T]
    float* __restrict__ out)
{
    const int wid  = threadIdx.x >> 5;
    const int lane = threadIdx.x & 31;
    const int n    = blockIdx.x * 8 + wid;

    const float* psrow  = ps  + (long)n * TLEN;
    const int*   ytrow  = yt  + (long)n * TLEN;
    const float* lcprow = lcp + (long)n * TLEN * CCLS;

    // ---------- coalesced loads: y_true, then ps[t+1], then gathers ----------
    int yv[STRIPS];
#pragma unroll
    for (int k = 0; k < STRIPS; k++) {
        int tc = min(32 * k + lane, TLEN - 1);
        yv[k] = __ldg(ytrow + tc);
    }

    float pv[STRIPS];                    // pv[k] = ps[t+1] (clamped; unused when t >= T-1)
#pragma unroll
    for (int k = 0; k < STRIPS; k++) {
        int t1 = min(32 * k + lane + 1, TLEN - 1);
        pv[k] = __ldg(psrow + t1);
    }

    float yh[STRIPS];                    // gather: 32 consecutive 128B rows per step
#pragma unroll
    for (int k = 0; k < STRIPS; k++) {
        int tc = min(32 * k + lane, TLEN - 1);
        yh[k] = __ldg(lcprow + tc * CCLS + yv[k]);
    }

    // ---------- strip-wise product scan + fused epilogue ----------
    float carry = 1.0f;                  // product of q over all previous strips
    float ce = 0.0f, er = 0.0f;
#pragma unroll
    for (int k = 0; k < STRIPS; k++) {
        const int t = 32 * k + lane;
        float q = (t < TLEN - 1) ? (1.0f - pv[k]) : 1.0f;

        // inclusive product scan within the strip
        float incl = q;
#pragma unroll
        for (int off = 1; off < 32; off <<= 1) {
            float up = __shfl_up_sync(0xffffffffu, incl, off);
            if (lane >= off) incl *= up;
        }
        float excl = __shfl_up_sync(0xffffffffu, incl, 1);
        if (lane == 0) excl = 1.0f;

        float B = carry * excl;          // exclusive prefix product up to t
        carry *= __shfl_sync(0xffffffffu, incl, 31);   // strip total

        if (t < TLEN) {
            float Pt = ((t < TLEN - 1) ? pv[k] * B : B) + EPS_O_T;
            float p  = __expf(yh[k]);
            er = fmaf(Pt * p, 1.0f - (float)t * INV_T, er);
            ce = fmaf(-yh[k], Pt, ce);
        }
    }

    // ---------- warp reduce -> per-row value ----------
#pragma unroll
    for (int off = 16; off; off >>= 1) {
        ce += __shfl_down_sync(0xffffffffu, ce, off);
        er += __shfl_down_sync(0xffffffffu, er, off);
    }

    __shared__ float ssum[8];
    __shared__ bool  s_last;
    if (lane == 0)
        ssum[wid] = ALPHA_F * ce - (1.0f - ALPHA_F) * er;
    __syncthreads();

    // ---------- block sum + last-block final reduction ----------
    if (threadIdx.x == 0) {
        float bs = 0.0f;
#pragma unroll
        for (int i = 0; i < 8; i++) bs += ssum[i];
        g_block[blockIdx.x] = bs;
        __threadfence();
        unsigned int ticket = atomicAdd(&g_count, 1u);
        s_last = (ticket == NBLK - 1);
    }
    __syncthreads();

    if (s_last) {
        float t0 = g_block[threadIdx.x] + g_block[threadIdx.x + 256];
        __shared__ float sh[256];
        sh[threadIdx.x] = t0;
        __syncthreads();
        for (int w = 128; w >= 32; w >>= 1) {
            if (threadIdx.x < w) sh[threadIdx.x] += sh[threadIdx.x + w];
            __syncthreads();
        }
        if (threadIdx.x < 32) {
            float r = sh[threadIdx.x];
#pragma unroll
            for (int off = 16; off; off >>= 1)
                r += __shfl_down_sync(0xffffffffu, r, off);
            if (threadIdx.x == 0) {
                out[0] = r * (1.0f / (float)NROWS);
                g_count = 0;               // reset for next graph replay
            }
        }
    }
}

extern "C" void kernel_launch(void* const* d_in, const int* in_sizes, int n_in,
                              void* d_out, int out_size)
{
    const float* lcp = (const float*)d_in[0];  // [N,T,C] f32
    const float* ps  = (const float*)d_in[1];  // [N,T]   f32
    const int*   yt  = (const int*)  d_in[2];  // [N,T]   i32
    float* out = (float*)d_out;

    fused_kernel<<<NBLK, 256>>>(lcp, ps, yt, out);
}